// round 13
// baseline (speedup 1.0000x reference)
#include <cuda_runtime.h>

// TSM temporal shift: x (128, 96, 56, 56) f32, N_FRAME=8, fold=32.
//   c in [0,32):  out[b,t] = x[b,t+1]  (0 at t=7)
//   c in [32,64): out[b,t] = x[b,t-1]  (0 at t=0)
//   c in [64,96): copy
// R6: launch-order probe at the HBM copy-roofline. Collapse (group, xchunk)
// into blockIdx.x (fast dim) so consecutive CTAs in a wave sweep each output
// bt-slice CONTIGUOUSLY (301 KB linear writes, reads from +-1 slice likewise
// linear) -> max DRAM row-buffer locality per wave. g/xb derivation is
// block-uniform (one divide per CTA). TPB=128, V=7, exact cover.

static constexpr int HW4     = (56 * 56) / 4;   // 784 float4 per channel plane
static constexpr int G4      = 32 * HW4;        // 25088 float4 per group per bt
static constexpr int PER_BT4 = 3 * G4;          // 75264 float4 per bt slice
static constexpr int V       = 7;               // float4 per thread
static constexpr int TPB     = 128;
static constexpr int XPG     = G4 / (V * TPB);  // 28 x-chunks per group, exact

__global__ __launch_bounds__(TPB) void tsm_kernel(const float4* __restrict__ in,
                                                  float4* __restrict__ out) {
    // blockIdx.x in [0, 84): fast dim sweeps the whole bt-slice in address order.
    const int g  = blockIdx.x / XPG;   // block-uniform
    const int xb = blockIdx.x - g * XPG;
    const int bt = blockIdx.y;
    const int t  = bt & 7;             // frame within clip of 8

    // Block-uniform source shift and validity.
    const int  dt    = (g == 0) ? 1 : ((g == 1) ? -1 : 0);
    const bool valid = (g == 2) || ((g == 0) ? (t < 7) : (t > 0));

    const int chunk = g * G4 + xb * (V * TPB) + threadIdx.x;
    const float4* src = in  + (bt + dt) * PER_BT4 + chunk;
    float4*       dst = out + bt * PER_BT4 + chunk;

    float4 v[V];
    if (valid) {
        // Front-batched loads: 7 independent LDG.128 in flight per thread.
        #pragma unroll
        for (int k = 0; k < V; k++) v[k] = __ldcs(src + k * TPB);
    } else {
        #pragma unroll
        for (int k = 0; k < V; k++) v[k] = make_float4(0.f, 0.f, 0.f, 0.f);
    }

    #pragma unroll
    for (int k = 0; k < V; k++) __stcs(dst + k * TPB, v[k]);
}

extern "C" void kernel_launch(void* const* d_in, const int* in_sizes, int n_in,
                              void* d_out, int out_size) {
    const float4* in  = (const float4*)d_in[0];
    float4*       out = (float4*)d_out;

    dim3 grid(3 * XPG, 128);   // (84, 128) = 10752 blocks, exact cover
    tsm_kernel<<<grid, TPB>>>(in, out);
}